// round 1
// baseline (speedup 1.0000x reference)
#include <cuda_runtime.h>
#include <cuda_bf16.h>
#include <cstdint>

#define N_NODES   100000
#define N_EDGES   1600000
#define IN_DIM    128
#define DIM_H     64
#define N_GRAPHS  64

// -------- device scratch (no cudaMalloc allowed) --------
__device__ float g_t  [(size_t)N_NODES * DIM_H];   // h @ Wa (pre-aggregation)
__device__ float g_agg[(size_t)N_NODES * DIM_H];   // t + sum_{j->i} t_j
__device__ float g_h  [(size_t)N_NODES * DIM_H];   // layer output
__device__ int   g_src[N_EDGES];
__device__ int   g_dst[N_EDGES];
__device__ int   g_batch[N_NODES];
__device__ float g_pooled[N_GRAPHS * DIM_H];
__device__ int   g_is64_edge;
__device__ int   g_is64_batch;

// -------- dtype detection (int64 vs int32 index arrays) --------
__global__ void detect_kernel(const void* edge, const void* batch) {
    if (threadIdx.x == 0 && blockIdx.x == 0) {
        const long long* e = (const long long*)edge;
        int ok = 1;
        for (int k = 0; k < 64; k++) {
            long long v = e[k * 997 + 5];
            if (v < 0 || v >= (long long)N_NODES) ok = 0;
        }
        g_is64_edge = ok;
        const long long* b = (const long long*)batch;
        int ok2 = 1;
        for (int k = 0; k < 64; k++) {
            long long v = b[N_NODES / 4 + k * 331];   // mid-array: batch is sorted
            if (v < 0 || v >= (long long)N_GRAPHS) ok2 = 0;
        }
        g_is64_batch = ok2;
    }
}

__global__ void convert_kernel(const void* edge, const void* batch) {
    int i = blockIdx.x * blockDim.x + threadIdx.x;
    int e64 = g_is64_edge, b64 = g_is64_batch;
    if (i < N_EDGES) {
        if (e64) {
            g_src[i] = (int)((const long long*)edge)[i];
            g_dst[i] = (int)((const long long*)edge)[i + N_EDGES];
        } else {
            g_src[i] = ((const int*)edge)[i];
            g_dst[i] = ((const int*)edge)[i + N_EDGES];
        }
    }
    if (i < N_NODES) {
        g_batch[i] = b64 ? (int)((const long long*)batch)[i]
                         : ((const int*)batch)[i];
    }
}

// -------- fused GEMM: C[M,64] = f(A)[M,K] @ W[K,64], 64x64 tile, 256 thr --------
// POST=false: C = A @ W, stored to out1 AND out2 (agg init).
// POST=true : A' = relu(A*c1[k] + c0[k]) (BN+bias+ReLU prologue),
//             C  = relu(A' @ W + bb),    stored to out1.
template<int K, bool POST>
__global__ void __launch_bounds__(256) gemm64_kernel(
    const float* __restrict__ A, const float* __restrict__ W,
    const float* __restrict__ p_ba, const float* __restrict__ p_g,
    const float* __restrict__ p_be, const float* __restrict__ p_bb,
    float* __restrict__ out1, float* __restrict__ out2, int M)
{
    __shared__ float As[16][64];
    __shared__ float Ws[16][64];
    __shared__ float c0[64], c1[64], cb[64];

    const int tid = threadIdx.x;
    if (POST) {
        if (tid < 64) {
            const float S = 0.99999500003749969f;   // 1/sqrt(1+1e-5)
            float cc1 = S * p_g[tid];
            c1[tid] = cc1;
            c0[tid] = fmaf(p_ba[tid], cc1, p_be[tid]);
            cb[tid] = p_bb[tid];
        }
        __syncthreads();
    }

    const int row0 = blockIdx.x * 64;
    const int tx = tid & 15;        // col group (4 cols)
    const int ty = tid >> 4;        // row group (4 rows)
    const int ar = tid >> 2;        // A-stage row 0..63
    const int ac = (tid & 3) * 4;   // A-stage k offset 0,4,8,12
    const int wr = tid >> 4;        // W-stage k row 0..15
    const int wc = (tid & 15) * 4;  // W-stage col

    float acc[4][4] = {};

    #pragma unroll
    for (int kt = 0; kt < K / 16; kt++) {
        float4 v = make_float4(0.f, 0.f, 0.f, 0.f);
        int row = row0 + ar;
        if (row < M)
            v = *(const float4*)&A[(size_t)row * K + kt * 16 + ac];
        if (POST) {
            int kk = kt * 16 + ac;
            v.x = fmaxf(fmaf(v.x, c1[kk + 0], c0[kk + 0]), 0.f);
            v.y = fmaxf(fmaf(v.y, c1[kk + 1], c0[kk + 1]), 0.f);
            v.z = fmaxf(fmaf(v.z, c1[kk + 2], c0[kk + 2]), 0.f);
            v.w = fmaxf(fmaf(v.w, c1[kk + 3], c0[kk + 3]), 0.f);
        }
        As[ac + 0][ar] = v.x;
        As[ac + 1][ar] = v.y;
        As[ac + 2][ar] = v.z;
        As[ac + 3][ar] = v.w;
        *(float4*)&Ws[wr][wc] = *(const float4*)&W[(size_t)(kt * 16 + wr) * 64 + wc];
        __syncthreads();

        #pragma unroll
        for (int k = 0; k < 16; k++) {
            float4 a = *(float4*)&As[k][ty * 4];
            float4 b = *(float4*)&Ws[k][tx * 4];
            acc[0][0] = fmaf(a.x, b.x, acc[0][0]);
            acc[0][1] = fmaf(a.x, b.y, acc[0][1]);
            acc[0][2] = fmaf(a.x, b.z, acc[0][2]);
            acc[0][3] = fmaf(a.x, b.w, acc[0][3]);
            acc[1][0] = fmaf(a.y, b.x, acc[1][0]);
            acc[1][1] = fmaf(a.y, b.y, acc[1][1]);
            acc[1][2] = fmaf(a.y, b.z, acc[1][2]);
            acc[1][3] = fmaf(a.y, b.w, acc[1][3]);
            acc[2][0] = fmaf(a.z, b.x, acc[2][0]);
            acc[2][1] = fmaf(a.z, b.y, acc[2][1]);
            acc[2][2] = fmaf(a.z, b.z, acc[2][2]);
            acc[2][3] = fmaf(a.z, b.w, acc[2][3]);
            acc[3][0] = fmaf(a.w, b.x, acc[3][0]);
            acc[3][1] = fmaf(a.w, b.y, acc[3][1]);
            acc[3][2] = fmaf(a.w, b.z, acc[3][2]);
            acc[3][3] = fmaf(a.w, b.w, acc[3][3]);
        }
        __syncthreads();
    }

    #pragma unroll
    for (int i = 0; i < 4; i++) {
        int row = row0 + ty * 4 + i;
        if (row >= M) break;
        float4 o = make_float4(acc[i][0], acc[i][1], acc[i][2], acc[i][3]);
        if (POST) {
            o.x = fmaxf(o.x + cb[tx * 4 + 0], 0.f);
            o.y = fmaxf(o.y + cb[tx * 4 + 1], 0.f);
            o.z = fmaxf(o.z + cb[tx * 4 + 2], 0.f);
            o.w = fmaxf(o.w + cb[tx * 4 + 3], 0.f);
        }
        *(float4*)&out1[(size_t)row * 64 + tx * 4] = o;
        if (!POST)
            *(float4*)&out2[(size_t)row * 64 + tx * 4] = o;
    }
}

// -------- edge aggregation: agg[dst] += t[src], 16 threads/edge, v4 red --------
__global__ void __launch_bounds__(256) edge_kernel(int nEdges) {
    int gid = blockIdx.x * blockDim.x + threadIdx.x;
    int e = gid >> 4;
    if (e >= nEdges) return;
    int lane = gid & 15;
    int s = g_src[e];
    int d = g_dst[e];
    float4 v = *(const float4*)&g_t[(size_t)s * 64 + lane * 4];
    float* p = &g_agg[(size_t)d * 64 + lane * 4];
    asm volatile("red.global.add.v4.f32 [%0], {%1,%2,%3,%4};"
                 :: "l"(p), "f"(v.x), "f"(v.y), "f"(v.z), "f"(v.w) : "memory");
}

// -------- pooling --------
__global__ void zero_pooled_kernel() {
    int i = blockIdx.x * blockDim.x + threadIdx.x;
    if (i < N_GRAPHS * DIM_H) g_pooled[i] = 0.f;
}

__global__ void __launch_bounds__(256) pool_kernel() {
    int gid = blockIdx.x * blockDim.x + threadIdx.x;
    int node = gid >> 4;
    if (node >= N_NODES) return;
    int lane = gid & 15;
    int gidx = g_batch[node];
    float4 v = *(const float4*)&g_h[(size_t)node * 64 + lane * 4];
    float* p = &g_pooled[gidx * 64 + lane * 4];
    asm volatile("red.global.add.v4.f32 [%0], {%1,%2,%3,%4};"
                 :: "l"(p), "f"(v.x), "f"(v.y), "f"(v.z), "f"(v.w) : "memory");
}

// -------- classifier: hp@(sum of 3 Wl1 blocks)+bl1, relu, @Wl2+bl2, log_softmax --------
__global__ void __launch_bounds__(256) classifier_kernel(
    const float* __restrict__ Wl1, const float* __restrict__ bl1,
    const float* __restrict__ Wl2, const float* __restrict__ bl2,
    float* __restrict__ out)
{
    __shared__ float sHp[64 * 64];
    __shared__ float sWs[64 * 64];
    const int tid = threadIdx.x;
    for (int i = tid; i < 4096; i += 256) {
        sHp[i] = g_pooled[i];
        sWs[i] = Wl1[i] + Wl1[4096 + i] + Wl1[8192 + i];
    }
    __syncthreads();
    float z1r[16];
    #pragma unroll
    for (int u = 0; u < 16; u++) {
        int i = tid + u * 256;
        int gr = i >> 6, c = i & 63;
        float acc = bl1[c];
        #pragma unroll
        for (int k = 0; k < 64; k++)
            acc = fmaf(sHp[gr * 64 + k], sWs[k * 64 + c], acc);
        z1r[u] = fmaxf(acc, 0.f);
    }
    __syncthreads();
    #pragma unroll
    for (int u = 0; u < 16; u++)
        sHp[tid + u * 256] = z1r[u];   // reuse sHp as z1
    __syncthreads();
    if (tid < 64) {
        int gr = tid;
        float z0 = bl2[0], z1v = bl2[1];
        #pragma unroll
        for (int c = 0; c < 64; c++) {
            float z = sHp[gr * 64 + c];
            z0  = fmaf(z, Wl2[c * 2 + 0], z0);
            z1v = fmaf(z, Wl2[c * 2 + 1], z1v);
        }
        float m = fmaxf(z0, z1v);
        float l = m + logf(expf(z0 - m) + expf(z1v - m));
        out[gr * 2 + 0] = z0 - l;
        out[gr * 2 + 1] = z1v - l;
    }
}

// -------- launch --------
extern "C" void kernel_launch(void* const* d_in, const int* in_sizes, int n_in,
                              void* d_out, int out_size)
{
    const float* x    = (const float*)d_in[0];
    const void*  ei   = d_in[1];
    const void*  bat  = d_in[2];
    const float* W0a  = (const float*)d_in[3];
    const float* b0a  = (const float*)d_in[4];
    const float* g0   = (const float*)d_in[5];
    const float* be0  = (const float*)d_in[6];
    const float* W0b  = (const float*)d_in[7];
    const float* b0b  = (const float*)d_in[8];
    const float* Wsa  = (const float*)d_in[9];
    const float* bsa  = (const float*)d_in[10];
    const float* gs   = (const float*)d_in[11];
    const float* bes  = (const float*)d_in[12];
    const float* Wsb  = (const float*)d_in[13];
    const float* bsb  = (const float*)d_in[14];
    const float* Wl1  = (const float*)d_in[15];
    const float* bl1  = (const float*)d_in[16];
    const float* Wl2  = (const float*)d_in[17];
    const float* bl2  = (const float*)d_in[18];
    float* out = (float*)d_out;

    float *d_t, *d_agg, *d_h;
    cudaGetSymbolAddress((void**)&d_t,   g_t);
    cudaGetSymbolAddress((void**)&d_agg, g_agg);
    cudaGetSymbolAddress((void**)&d_h,   g_h);

    const int M = N_NODES;
    const int gemm_blocks = (M + 63) / 64;
    const int edge_threads = N_EDGES * 16;
    const int edge_blocks = (edge_threads + 255) / 256;
    const int pool_threads = N_NODES * 16;
    const int pool_blocks = (pool_threads + 255) / 256;

    detect_kernel<<<1, 32>>>(ei, bat);
    convert_kernel<<<(N_EDGES + 255) / 256, 256>>>(ei, bat);

    // Layer 0: t = x @ W0a  (K=128), agg = t
    gemm64_kernel<128, false><<<gemm_blocks, 256>>>(
        x, W0a, nullptr, nullptr, nullptr, nullptr, d_t, d_agg, M);
    edge_kernel<<<edge_blocks, 256>>>(N_EDGES);
    gemm64_kernel<64, true><<<gemm_blocks, 256>>>(
        d_agg, W0b, b0a, g0, be0, b0b, d_h, nullptr, M);

    // Layers 1..2
    for (int l = 0; l < 2; l++) {
        gemm64_kernel<64, false><<<gemm_blocks, 256>>>(
            d_h, Wsa + (size_t)l * 4096, nullptr, nullptr, nullptr, nullptr,
            d_t, d_agg, M);
        edge_kernel<<<edge_blocks, 256>>>(N_EDGES);
        gemm64_kernel<64, true><<<gemm_blocks, 256>>>(
            d_agg, Wsb + (size_t)l * 4096, bsa + l * 64, gs + l * 64,
            bes + l * 64, bsb + l * 64, d_h, nullptr, M);
    }

    zero_pooled_kernel<<<16, 256>>>();
    pool_kernel<<<pool_blocks, 256>>>();
    classifier_kernel<<<1, 256>>>(Wl1, bl1, Wl2, bl2, out);
}